// round 12
// baseline (speedup 1.0000x reference)
#include <cuda_runtime.h>
#include <cstdint>

// Problem constants (fixed by setup_inputs)
#define BB 4
#define CC 128
#define HH 96
#define WW 160
#define RR 4
#define SS 17   // 1 + 4*R

// Tiling
#define TW 32
#define TH 8
#define BX 16          // threads in w (2 px each)
#define BY 8
#define NTHREADS (BX * BY)   // 128
#define HALO_W (TW + 2 * RR) // 40
#define HALO_H (TH + 2 * RR) // 16
#define HALO_N (HALO_H * HALO_W)  // 640 floats per channel
#define HALO_Q (HALO_N / 4)       // 160 float4 quads
#define HALO_QW (HALO_W / 4)      // 10 quads per row

#define NCHUNK 4
#define CPK (CC / NCHUNK)    // 32 channels per chunk
#define STAGE_CH 4           // channels per pipeline stage
#define NSTAGE (CPK / STAGE_CH)  // 8 stages
#define HW (HH * WW)

// packed f32x2 fma: acc = a*b + acc
__device__ __forceinline__ void ffma2(uint64_t& acc, uint64_t a, uint64_t b) {
    asm("fma.rn.f32x2 %0, %1, %2, %0;" : "+l"(acc) : "l"(a), "l"(b));
}
__device__ __forceinline__ uint64_t pack2(float lo, float hi) {
    uint64_t r;
    asm("mov.b64 %0, {%1, %2};" : "=l"(r) : "f"(lo), "f"(hi));
    return r;
}
__device__ __forceinline__ void cp_async16(uint32_t saddr, const void* gaddr, int sz) {
    asm volatile("cp.async.ca.shared.global [%0], [%1], 16, %2;"
                 :: "r"(saddr), "l"(gaddr), "r"(sz) : "memory");
}

__global__ __launch_bounds__(NTHREADS, 8)
void cost_volume_kernel(const float* __restrict__ src,
                        const float* __restrict__ tgt,
                        float* __restrict__ out) {
    // tgt halo double buffer: 2 * 4 * 640 * 4B = 20 KB
    __shared__ float smT[2][STAGE_CH * HALO_N];

    const int tx = threadIdx.x;
    const int ty = threadIdx.y;
    const int tid = ty * BX + tx;
    const int w0 = blockIdx.x * TW;
    const int h0 = blockIdx.y * TH;
    const int b     = blockIdx.z >> 2;   // NCHUNK = 4
    const int chunk = blockIdx.z & 3;
    const int c0 = chunk * CPK;
    const int lx = 2 * tx;
    const int w  = w0 + lx;
    const int h  = h0 + ty;

    const float* tgtb = tgt + ((long long)b * CC + c0) * HW;
    const float* srcp = src + (((long long)b * CC + c0) * HH + h) * WW + w;

    // staging offsets (channel-invariant): 160 quads / 128 threads -> 2 slots
    int goff[2], szv[2];
#pragma unroll
    for (int k = 0; k < 2; k++) {
        int pos4 = tid + k * NTHREADS;   // quad index (k=1 valid for tid<32)
        int r    = pos4 / HALO_QW;
        int c4   = pos4 - r * HALO_QW;
        int gr   = h0 - RR + r;
        int gc   = w0 - RR + 4 * c4;     // 16B aligned; quad fully in or fully out
        bool ok  = ((unsigned)gr < (unsigned)HH) & ((unsigned)gc < (unsigned)WW);
        goff[k] = gr * WW + gc;
        szv[k]  = ok ? 16 : 0;
    }
    const uint32_t stbase = (uint32_t)__cvta_generic_to_shared(&smT[0][0]);
    const bool k1on = tid < HALO_Q - NTHREADS;   // tid < 32

    auto stage_load = [&](int st) {
        const uint32_t sb = stbase + (st & 1) * (STAGE_CH * HALO_N * 4);
        const float* tb = tgtb + st * STAGE_CH * HW;
#pragma unroll
        for (int ch = 0; ch < STAGE_CH; ch++) {
            const float* tc = tb + ch * HW;
            const uint32_t sc = sb + ch * (HALO_N * 4);
            cp_async16(sc + tid * 16, tc + goff[0], szv[0]);
            if (k1on)
                cp_async16(sc + (tid + NTHREADS) * 16, tc + goff[1], szv[1]);
        }
        asm volatile("cp.async.commit_group;" ::: "memory");
    };

    stage_load(0);

    uint64_t acc[SS];
#pragma unroll
    for (int s = 0; s < SS; s++) acc[s] = 0ull;

    const int rowbase = (ty + RR) * HALO_W + lx;
    uint64_t sv_cur = *(const uint64_t*)(srcp);   // channel 0 src pair

#pragma unroll 1
    for (int st = 0; st < NSTAGE; st++) {
        if (st + 1 < NSTAGE) {
            stage_load(st + 1);
            asm volatile("cp.async.wait_group 1;" ::: "memory");
        } else {
            asm volatile("cp.async.wait_group 0;" ::: "memory");
        }
        __syncthreads();

        const float* smb = &smT[st & 1][0];
#pragma unroll
        for (int ch = 0; ch < STAGE_CH; ch++) {
            const int gch = st * STAGE_CH + ch;
            uint64_t sv_nxt = 0ull;
            if (gch + 1 < CPK)
                sv_nxt = *(const uint64_t*)(srcp + (gch + 1) * HW);

            const float* smc = smb + ch * HALO_N;
            float2 t0 = *(const float2*)(smc + rowbase + 0);
            float2 t1 = *(const float2*)(smc + rowbase + 2);
            float2 t2 = *(const float2*)(smc + rowbase + 4);
            float2 t3 = *(const float2*)(smc + rowbase + 6);
            float2 t4 = *(const float2*)(smc + rowbase + 8);

            ffma2(acc[0],  sv_cur, pack2(t2.x, t2.y));
            ffma2(acc[3],  sv_cur, pack2(t1.y, t2.x));
            ffma2(acc[4],  sv_cur, pack2(t2.y, t3.x));
            ffma2(acc[7],  sv_cur, pack2(t1.x, t1.y));
            ffma2(acc[8],  sv_cur, pack2(t3.x, t3.y));
            ffma2(acc[11], sv_cur, pack2(t0.y, t1.x));
            ffma2(acc[12], sv_cur, pack2(t3.y, t4.x));
            ffma2(acc[15], sv_cur, pack2(t0.x, t0.y));
            ffma2(acc[16], sv_cur, pack2(t4.x, t4.y));

#pragma unroll
            for (int i2 = 1; i2 <= RR; i2++) {
                uint64_t tu = *(const uint64_t*)(smc + (ty + RR - i2) * HALO_W + lx + RR);
                uint64_t td = *(const uint64_t*)(smc + (ty + RR + i2) * HALO_W + lx + RR);
                ffma2(acc[4 * i2 - 3], sv_cur, tu);
                ffma2(acc[4 * i2 - 2], sv_cur, td);
            }
            sv_cur = sv_nxt;
        }
        __syncthreads();   // buffer reuse fence before next stage overwrite
    }

    // combine partials across chunks via float2 atomics
    float* ob = out + ((((long long)b * SS) * HH) + h) * WW + w;
#pragma unroll
    for (int s = 0; s < SS; s++) {
        float2 o;
        asm("mov.b64 {%0, %1}, %2;" : "=f"(o.x), "=f"(o.y) : "l"(acc[s]));
        atomicAdd((float2*)(ob + s * HW), o);
    }
}

extern "C" void kernel_launch(void* const* d_in, const int* in_sizes, int n_in,
                              void* d_out, int out_size) {
    const float* src = (const float*)d_in[0];
    const float* tgt = (const float*)d_in[1];
    float* out = (float*)d_out;

    cudaMemsetAsync(out, 0, (size_t)out_size * sizeof(float), 0);

    dim3 block(BX, BY);
    dim3 grid(WW / TW, HH / TH, BB * NCHUNK);   // 5 x 12 x 16 = 960 CTAs
    cost_volume_kernel<<<grid, block>>>(src, tgt, out);
}

// round 13
// speedup vs baseline: 1.2750x; 1.2750x over previous
#include <cuda_runtime.h>
#include <cstdint>

// Problem constants (fixed by setup_inputs)
#define BB 4
#define CC 128
#define HH 96
#define WW 160
#define RR 4
#define SS 17   // 1 + 4*R

// Tiling
#define TW 32
#define TH 8
#define BX 16          // threads in w (2 px each)
#define BY 8
#define NTHREADS (BX * BY)   // 128
#define HALO_W (TW + 2 * RR) // 40
#define HALO_H (TH + 2 * RR) // 16
#define HALO_N (HALO_H * HALO_W)  // 640 floats per channel
#define HALO_Q (HALO_N / 4)       // 160 float4 quads
#define HALO_QW (HALO_W / 4)      // 10 quads per row

#define NCHUNK 8
#define CPK (CC / NCHUNK)    // 16 channels per chunk
#define STAGE_CH 4           // channels per pipeline stage
#define NSTAGE (CPK / STAGE_CH)  // 4 stages
#define HW (HH * WW)

// packed f32x2 fma: acc = a*b + acc
__device__ __forceinline__ void ffma2(uint64_t& acc, uint64_t a, uint64_t b) {
    asm("fma.rn.f32x2 %0, %1, %2, %0;" : "+l"(acc) : "l"(a), "l"(b));
}
__device__ __forceinline__ uint64_t pack2(float lo, float hi) {
    uint64_t r;
    asm("mov.b64 %0, {%1, %2};" : "=l"(r) : "f"(lo), "f"(hi));
    return r;
}
__device__ __forceinline__ void cp_async16(uint32_t saddr, const void* gaddr, int sz) {
    asm volatile("cp.async.ca.shared.global [%0], [%1], 16, %2;"
                 :: "r"(saddr), "l"(gaddr), "r"(sz) : "memory");
}

__global__ __launch_bounds__(NTHREADS, 8)
void cost_volume_kernel(const float* __restrict__ src,
                        const float* __restrict__ tgt,
                        float* __restrict__ out) {
    // tgt halo double buffer: 2 * 4 * 640 * 4B = 20 KB
    __shared__ float smT[2][STAGE_CH * HALO_N];

    const int tx = threadIdx.x;
    const int ty = threadIdx.y;
    const int tid = ty * BX + tx;
    const int w0 = blockIdx.x * TW;
    const int h0 = blockIdx.y * TH;
    const int b     = blockIdx.z >> 3;   // NCHUNK = 8
    const int chunk = blockIdx.z & 7;
    const int c0 = chunk * CPK;
    const int lx = 2 * tx;
    const int w  = w0 + lx;
    const int h  = h0 + ty;

    const float* tgtb = tgt + ((long long)b * CC + c0) * HW;
    const float* srcp = src + (((long long)b * CC + c0) * HH + h) * WW + w;

    // staging offsets (channel-invariant): 160 quads / 128 threads -> 2 slots
    // quads are 16B-aligned in gmem (w0-4 multiple of 4, W=160) and each quad
    // is fully in-bounds or fully out -> one zfill predicate per quad
    int goff[2], szv[2];
#pragma unroll
    for (int k = 0; k < 2; k++) {
        int pos4 = tid + k * NTHREADS;   // quad index (k=1 valid for tid<32)
        int r    = pos4 / HALO_QW;
        int c4   = pos4 - r * HALO_QW;
        int gr   = h0 - RR + r;
        int gc   = w0 - RR + 4 * c4;
        bool ok  = ((unsigned)gr < (unsigned)HH) & ((unsigned)gc < (unsigned)WW);
        goff[k] = gr * WW + gc;
        szv[k]  = ok ? 16 : 0;
    }
    const uint32_t stbase = (uint32_t)__cvta_generic_to_shared(&smT[0][0]);
    const bool k1on = tid < HALO_Q - NTHREADS;   // tid < 32

    auto stage_load = [&](int st) {
        const uint32_t sb = stbase + (st & 1) * (STAGE_CH * HALO_N * 4);
        const float* tb = tgtb + st * STAGE_CH * HW;
#pragma unroll
        for (int ch = 0; ch < STAGE_CH; ch++) {
            const float* tc = tb + ch * HW;
            const uint32_t sc = sb + ch * (HALO_N * 4);
            cp_async16(sc + tid * 16, tc + goff[0], szv[0]);
            if (k1on)
                cp_async16(sc + (tid + NTHREADS) * 16, tc + goff[1], szv[1]);
        }
        asm volatile("cp.async.commit_group;" ::: "memory");
    };

    stage_load(0);

    uint64_t acc[SS];
#pragma unroll
    for (int s = 0; s < SS; s++) acc[s] = 0ull;

    const int rowbase = (ty + RR) * HALO_W + lx;
    uint64_t sv_cur = *(const uint64_t*)(srcp);   // channel 0 src pair

#pragma unroll
    for (int st = 0; st < NSTAGE; st++) {
        if (st + 1 < NSTAGE) {
            stage_load(st + 1);
            asm volatile("cp.async.wait_group 1;" ::: "memory");
        } else {
            asm volatile("cp.async.wait_group 0;" ::: "memory");
        }
        __syncthreads();

        const float* smb = &smT[st & 1][0];
#pragma unroll
        for (int ch = 0; ch < STAGE_CH; ch++) {
            const int gch = st * STAGE_CH + ch;
            uint64_t sv_nxt = 0ull;
            if (gch + 1 < CPK)
                sv_nxt = *(const uint64_t*)(srcp + (gch + 1) * HW);

            const float* smc = smb + ch * HALO_N;
            float2 t0 = *(const float2*)(smc + rowbase + 0);
            float2 t1 = *(const float2*)(smc + rowbase + 2);
            float2 t2 = *(const float2*)(smc + rowbase + 4);
            float2 t3 = *(const float2*)(smc + rowbase + 6);
            float2 t4 = *(const float2*)(smc + rowbase + 8);

            ffma2(acc[0],  sv_cur, pack2(t2.x, t2.y));
            ffma2(acc[3],  sv_cur, pack2(t1.y, t2.x));
            ffma2(acc[4],  sv_cur, pack2(t2.y, t3.x));
            ffma2(acc[7],  sv_cur, pack2(t1.x, t1.y));
            ffma2(acc[8],  sv_cur, pack2(t3.x, t3.y));
            ffma2(acc[11], sv_cur, pack2(t0.y, t1.x));
            ffma2(acc[12], sv_cur, pack2(t3.y, t4.x));
            ffma2(acc[15], sv_cur, pack2(t0.x, t0.y));
            ffma2(acc[16], sv_cur, pack2(t4.x, t4.y));

#pragma unroll
            for (int i2 = 1; i2 <= RR; i2++) {
                uint64_t tu = *(const uint64_t*)(smc + (ty + RR - i2) * HALO_W + lx + RR);
                uint64_t td = *(const uint64_t*)(smc + (ty + RR + i2) * HALO_W + lx + RR);
                ffma2(acc[4 * i2 - 3], sv_cur, tu);
                ffma2(acc[4 * i2 - 2], sv_cur, td);
            }
            sv_cur = sv_nxt;
        }
        __syncthreads();   // buffer reuse fence before next stage overwrite
    }

    // combine partials across chunks via float2 atomics
    float* ob = out + ((((long long)b * SS) * HH) + h) * WW + w;
#pragma unroll
    for (int s = 0; s < SS; s++) {
        float2 o;
        asm("mov.b64 {%0, %1}, %2;" : "=f"(o.x), "=f"(o.y) : "l"(acc[s]));
        atomicAdd((float2*)(ob + s * HW), o);
    }
}

extern "C" void kernel_launch(void* const* d_in, const int* in_sizes, int n_in,
                              void* d_out, int out_size) {
    const float* src = (const float*)d_in[0];
    const float* tgt = (const float*)d_in[1];
    float* out = (float*)d_out;

    cudaMemsetAsync(out, 0, (size_t)out_size * sizeof(float), 0);

    dim3 block(BX, BY);
    dim3 grid(WW / TW, HH / TH, BB * NCHUNK);   // 5 x 12 x 32 = 1920 CTAs
    cost_volume_kernel<<<grid, block>>>(src, tgt, out);
}